// round 11
// baseline (speedup 1.0000x reference)
#include <cuda_runtime.h>
#include <math.h>
#include <float.h>

#define BATCH   256
#define NLEV    4
#define CDIM    8000
#define NTOTAL  10500
#define THREADS 512

// Packed accumulator: bits [0,48) fixed-point sum (x 2^32, all p >= 0),
// bits [48,..) arrival count. Integer adds commute exactly -> deterministic.
__device__ unsigned long long g_acc = 0ULL;

// Sweep: exp-sum + value-max only (no index tracking -> no select chains).
template<int N4, int STRIDE, int ITERS, bool NEED_SUM>
__device__ __forceinline__ void sweep_level(const float4* __restrict__ row4,
                                            int lt, float& s, float& m) {
    float s0 = 0.f, s1 = 0.f, s2 = 0.f, s3 = 0.f;
    float m0 = -FLT_MAX, m1 = -FLT_MAX, m2 = -FLT_MAX, m3 = -FLT_MAX;
    #pragma unroll
    for (int k = 0; k < ITERS; k++) {
        int idx = lt + k * STRIDE;
        bool p  = idx < N4;
        int  id = p ? idx : (N4 - 1);
        float4 w = __ldg(&row4[id]);
        if (!p) { w.x = w.y = w.z = w.w = -FLT_MAX; }
        if (NEED_SUM) {
            s0 += __expf(w.x); s1 += __expf(w.y);
            s2 += __expf(w.z); s3 += __expf(w.w);
        }
        m0 = fmaxf(m0, w.x); m1 = fmaxf(m1, w.y);
        m2 = fmaxf(m2, w.z); m3 = fmaxf(m3, w.w);
    }
    s = (s0 + s1) + (s2 + s3);
    m = fmaxf(fmaxf(m0, m1), fmaxf(m2, m3));
}

// Recheck: re-load (L1 hits) and recover the first index equal to the block max.
// atomicMin keeps jnp.argmax first-max semantics even under exact ties.
template<int N4, int STRIDE, int ITERS>
__device__ __forceinline__ void recheck_level(const float4* __restrict__ row4,
                                              int lt, float bmax, int* slot) {
    int best = 0x7fffffff;
    #pragma unroll
    for (int k = 0; k < ITERS; k++) {
        int idx = lt + k * STRIDE;
        int id  = (idx < N4) ? idx : (N4 - 1);   // clamped dup maps to same element
        float4 w = __ldg(&row4[id]);
        int e = 4 * id;
        if (w.x == bmax) best = min(best, e + 0);
        if (w.y == bmax) best = min(best, e + 1);
        if (w.z == bmax) best = min(best, e + 2);
        if (w.w == bmax) best = min(best, e + 3);
    }
    if (best != 0x7fffffff) atomicMin(slot, best);
}

__global__ void __launch_bounds__(THREADS, 2) fused_taxanet_kernel(
    const float* __restrict__ y_pred,
    const int*   __restrict__ y_true,
    const float* __restrict__ H,
    float*       __restrict__ out)
{
    const int b    = blockIdx.x;
    const int tid  = threadIdx.x;
    const int warp = tid >> 5;
    const int lane = tid & 31;

    __shared__ float s_s[16], s_m[16];
    __shared__ float s_tlogit[4];
    __shared__ float s_bmax[4];
    __shared__ float s_nll[4];
    __shared__ int   s_gidx[4];

    const float* base = y_pred + (size_t)b * NLEV * CDIM;

    // Segments: warps [0,8)->L3, [8,12)->L2, [12,14)->L1, [14]->L0, [15]->prefetch
    int j = 0, seg_base = 0;
    if (warp < 8)       { j = 3; seg_base = 0;  }
    else if (warp < 12) { j = 2; seg_base = 8;  }
    else if (warp < 14) { j = 1; seg_base = 12; }
    else if (warp < 15) { j = 0; seg_base = 14; }
    const int lt = tid - seg_base * 32;
    const float4* row4 = reinterpret_cast<const float4*>(base + (size_t)j * CDIM);

    if (warp == 15) {
        // Target-logit prefetch: two dependent trips, hidden behind the sweep.
        if (lane < 3) {
            const int jj  = lane + 1;
            const int szs = (jj == 1) ? 400 : (jj == 2) ? 2000 : 8000;
            int tgt = __ldg(&y_true[b * NLEV + jj]);
            tgt = min(max(tgt, 0), szs - 1);
            s_tlogit[jj] = __ldg(base + (size_t)jj * CDIM + tgt);
        }
        if (lane == 0) { s_s[15] = 0.f; s_m[15] = -FLT_MAX; }
        if (lane < 4)  { s_gidx[lane] = 0x7fffffff; }
    } else {
        float s, m;
        if (j == 3)      sweep_level<2000, 256, 8, true >(row4, lt, s, m);
        else if (j == 2) sweep_level< 500, 128, 4, true >(row4, lt, s, m);
        else if (j == 1) sweep_level< 100,  64, 2, true >(row4, lt, s, m);
        else             sweep_level<  25,  32, 1, false>(row4, lt, s, m);

        // Warp reduce (sum + max only — half the shuffle payload).
        #pragma unroll
        for (int o = 16; o > 0; o >>= 1) {
            s += __shfl_down_sync(0xffffffffu, s, o);
            m  = fmaxf(m, __shfl_down_sync(0xffffffffu, m, o));
        }
        if (lane == 0) { s_s[warp] = s; s_m[warp] = m; }
    }
    __syncthreads();   // barrier 1

    // Warp 0: segmented fold of 16 (sum, max) partials; heads publish bmax/nll.
    if (warp == 0) {
        float rs = 0.f, rm = -FLT_MAX;
        if (lane < 16) { rs = s_s[lane]; rm = s_m[lane]; }
        const int segsz   = (lane < 8) ? 8 : (lane < 12) ? 4 : (lane < 14) ? 2 : 1;
        const int segbase = (lane < 8) ? 0 : (lane < 12) ? 8 : (lane < 14) ? 12 : 14;
        const int w = lane - segbase;
        #pragma unroll
        for (int o = 4; o > 0; o >>= 1) {
            float s2 = __shfl_down_sync(0xffffffffu, rs, o);
            float m2 = __shfl_down_sync(0xffffffffu, rm, o);
            if (w + o < segsz) { rs += s2; rm = fmaxf(rm, m2); }
        }
        if (lane == 0)       { s_bmax[3] = rm; s_nll[3] = __logf(rs) - s_tlogit[3]; }
        else if (lane == 8)  { s_bmax[2] = rm; s_nll[2] = __logf(rs) - s_tlogit[2]; }
        else if (lane == 12) { s_bmax[1] = rm; s_nll[1] = __logf(rs) - s_tlogit[1]; }
        else if (lane == 14) { s_bmax[0] = rm; }
    }
    __syncthreads();   // barrier 2

    // Index recovery: re-loads hit L1 (42KB/block << 228KB).
    if (warp != 15) {
        const float bm = s_bmax[j];
        if (j == 3)      recheck_level<2000, 256, 8>(row4, lt, bm, &s_gidx[3]);
        else if (j == 2) recheck_level< 500, 128, 4>(row4, lt, bm, &s_gidx[2]);
        else if (j == 1) recheck_level< 100,  64, 2>(row4, lt, bm, &s_gidx[1]);
        else             recheck_level<  25,  32, 1>(row4, lt, bm, &s_gidx[0]);
    }
    __syncthreads();   // barrier 3

    // Tail: H gathers + one packed atomic.
    if (tid == 0) {
        const int g0 = s_gidx[0];
        const int g1 = s_gidx[1] + 100;
        const int g2 = s_gidx[2] + 500;
        const int g3 = s_gidx[3] + 2500;

        float h01 = __ldg(&H[(size_t)g0 * NTOTAL + g1]);
        float h12 = __ldg(&H[(size_t)g1 * NTOTAL + g2]);
        float h23 = __ldg(&H[(size_t)g2 * NTOTAL + g3]);
        float c01 = (h01 == 1.0f) ? 1.0f : 0.0f;
        float c12 = (h12 == 1.0f) ? 1.0f : 0.0f;
        float c23 = (h23 == 1.0f) ? 1.0f : 0.0f;

        const float E    = 2.7182817459106445f;   // float32(np.e)
        const float invB = 1.0f / (float)BATCH;
        float p = 0.25f * (E * c01 + s_nll[1] * invB)
                + 0.15f * (E * c12 + s_nll[2] * invB)
                + 0.10f * (E * c23 + s_nll[3] * invB);
        p = fmaxf(p, 0.0f);   // mathematically guaranteed; guards fixed-point

        unsigned long long fx =
            (unsigned long long)__float2ll_rn(p * 4294967296.0f);   // * 2^32
        unsigned long long old = atomicAdd(&g_acc, fx + (1ULL << 48));
        if ((old >> 48) == BATCH - 1) {
            unsigned long long tot = (old & 0xFFFFFFFFFFFFULL) + fx;
            out[0] = (float)((double)tot * (1.0 / 4294967296.0));
            g_acc = 0ULL;   // reset for graph replay
        }
    }
}

extern "C" void kernel_launch(void* const* d_in, const int* in_sizes, int n_in,
                              void* d_out, int out_size) {
    const float* y_pred = (const float*)d_in[0];
    const int*   y_true = (const int*)d_in[1];
    const float* H      = (const float*)d_in[2];
    float*       out    = (float*)d_out;

    fused_taxanet_kernel<<<BATCH, THREADS>>>(y_pred, y_true, H, out);
}